// round 9
// baseline (speedup 1.0000x reference)
#include <cuda_runtime.h>

#define N_NODES 50000
#define N_EDGES 800000
#define DIM 96

typedef unsigned long long ull;

// ---------------------------------------------------------------------------
// Scratch (__device__ globals per allocation-free rule)
// ---------------------------------------------------------------------------
__device__ __align__(128) float g_agg[N_NODES * DIM];   // normalized mean
__device__ int g_cnt[N_NODES];        // degree
__device__ int g_rowstart[N_NODES];   // CSR row offsets
__device__ int g_pos[N_NODES];        // fill cursors
__device__ int g_csr[N_EDGES];        // src node id per CSR slot

#define SCAN_T 512
#define SCAN_B 98                      // 98*512 = 50176 >= N_NODES
__device__ int g_bsum[SCAN_B];

// ---------------------------------------------------------------------------
// CSR build
// ---------------------------------------------------------------------------
__global__ void hist_kernel(const int* __restrict__ ei) {
    int e = blockIdx.x * blockDim.x + threadIdx.x;
    if (e < N_EDGES) atomicAdd(&g_cnt[ei[N_EDGES + e]], 1);
}

__global__ void scanA_kernel() {   // per-block exclusive scan + block sums
    __shared__ int s[SCAN_T];
    int tid = threadIdx.x;
    int i = blockIdx.x * SCAN_T + tid;
    int v = (i < N_NODES) ? g_cnt[i] : 0;
    s[tid] = v;
    __syncthreads();
    #pragma unroll
    for (int off = 1; off < SCAN_T; off <<= 1) {
        int t = (tid >= off) ? s[tid - off] : 0;
        __syncthreads();
        s[tid] += t;
        __syncthreads();
    }
    if (i < N_NODES) g_rowstart[i] = s[tid] - v;   // exclusive
    if (tid == SCAN_T - 1) g_bsum[blockIdx.x] = s[tid];
}

__global__ void scanB_kernel() {   // exclusive scan of 98 block sums
    __shared__ int s[128];
    int tid = threadIdx.x;
    int v = (tid < SCAN_B) ? g_bsum[tid] : 0;
    s[tid] = v;
    __syncthreads();
    #pragma unroll
    for (int off = 1; off < 128; off <<= 1) {
        int t = (tid >= off) ? s[tid - off] : 0;
        __syncthreads();
        s[tid] += t;
        __syncthreads();
    }
    if (tid < SCAN_B) g_bsum[tid] = s[tid] - v;
}

__global__ void scanC_kernel() {   // add block offsets; init cursors
    int i = blockIdx.x * blockDim.x + threadIdx.x;
    if (i < N_NODES) {
        int r = g_rowstart[i] + g_bsum[i / SCAN_T];
        g_rowstart[i] = r;
        g_pos[i] = r;
    }
}

__global__ void fill_kernel(const int* __restrict__ ei) {
    int e = blockIdx.x * blockDim.x + threadIdx.x;
    if (e < N_EDGES) {
        int src = ei[e];
        int dst = ei[N_EDGES + e];
        int slot = atomicAdd(&g_pos[dst], 1);
        g_csr[slot] = src;
    }
}

// ---------------------------------------------------------------------------
// Gather: 96 threads per node (2 nodes per 192-thread block).
// Thread j accumulates feature j over all neighbors, writes normalized mean.
// ---------------------------------------------------------------------------
__global__ void gather_kernel(const float* __restrict__ x) {
    int node = blockIdx.x * 2 + (threadIdx.x / 96);
    int j = threadIdx.x % 96;
    if (node >= N_NODES) return;

    int start = g_rowstart[node];
    int deg = g_cnt[node];
    int end = start + deg;

    float acc = 0.0f;
    int slot = start;
    for (; slot + 4 <= end; slot += 4) {
        int s0 = __ldg(&g_csr[slot + 0]);
        int s1 = __ldg(&g_csr[slot + 1]);
        int s2 = __ldg(&g_csr[slot + 2]);
        int s3 = __ldg(&g_csr[slot + 3]);
        float a0 = __ldg(&x[(size_t)s0 * DIM + j]);
        float a1 = __ldg(&x[(size_t)s1 * DIM + j]);
        float a2 = __ldg(&x[(size_t)s2 * DIM + j]);
        float a3 = __ldg(&x[(size_t)s3 * DIM + j]);
        acc += a0 + a1 + a2 + a3;
    }
    for (; slot < end; slot++) {
        int s0 = __ldg(&g_csr[slot]);
        acc += __ldg(&x[(size_t)s0 * DIM + j]);
    }

    float inv = 1.0f / fmaxf((float)deg, 1.0f);
    g_agg[(size_t)node * DIM + j] = acc * inv;
}

// ---------------------------------------------------------------------------
// GEMM half: out(+)= A @ W^T + bias.  BM=64, BN=96, full K=96, 128 threads,
// TM=8 x TN=6, packed fma.rn.f32x2. ACCUM: read-modify-write out.
// ---------------------------------------------------------------------------
#define BM 64
#define BN 96
#define TM 8
#define TN 6
#define GT 128
#define GEMM_BLOCKS ((N_NODES + BM - 1) / BM)   // 782
#define APITCH 100
#define BPITCH 49

__device__ __forceinline__ void ffma2(ull& d, ull a, ull b) {
    asm("fma.rn.f32x2 %0, %1, %2, %0;" : "+l"(d) : "l"(a), "l"(b));
}

template <bool ACCUM>
__global__ void gemm_half(const float* __restrict__ A,
                          const float* __restrict__ W,
                          const float* __restrict__ bias,
                          float* __restrict__ out) {
    __shared__ __align__(16) float  sA[BM][APITCH];
    __shared__ __align__(16) float2 sB[BN][BPITCH];

    const int tid = threadIdx.x;
    const int tx = tid % (BN / TN);     // 0..15
    const int ty = tid / (BN / TN);     // 0..7
    const int rowBase = blockIdx.x * BM;

    #pragma unroll
    for (int it = 0; it < 12; it++) {
        int idx = tid + it * GT;
        int m = idx / 24, q = idx % 24;
        int row = rowBase + m;
        float4 v = make_float4(0.f, 0.f, 0.f, 0.f);
        if (row < N_NODES)
            v = ((const float4*)(A + (size_t)row * DIM))[q];
        ((float4*)&sA[m][0])[q] = v;
    }
    #pragma unroll
    for (int it = 0; it < 18; it++) {
        int idx = tid + it * GT;
        int j = idx / 24, q = idx % 24;
        float4 v = *(const float4*)(W + (size_t)j * DIM + q * 4);
        sB[j][2 * q + 0] = make_float2(v.x, v.y);
        sB[j][2 * q + 1] = make_float2(v.z, v.w);
    }
    __syncthreads();

    ull acc2[TM][TN];
    #pragma unroll
    for (int i = 0; i < TM; i++)
        #pragma unroll
        for (int j = 0; j < TN; j++) acc2[i][j] = 0ULL;

    #pragma unroll 4
    for (int kp = 0; kp < DIM / 2; kp++) {
        ull a2[TM], b2[TN];
        #pragma unroll
        for (int i = 0; i < TM; i++)
            a2[i] = *(const ull*)&sA[ty * TM + i][2 * kp];
        #pragma unroll
        for (int j = 0; j < TN; j++)
            b2[j] = *(const ull*)&sB[tx * TN + j][kp];
        #pragma unroll
        for (int i = 0; i < TM; i++)
            #pragma unroll
            for (int j = 0; j < TN; j++)
                ffma2(acc2[i][j], a2[i], b2[j]);
    }

    const int colBase = tx * TN;
    #pragma unroll
    for (int i = 0; i < TM; i++) {
        int row = rowBase + ty * TM + i;
        if (row < N_NODES) {
            float r[TN];
            #pragma unroll
            for (int j = 0; j < TN; j++) {
                ull u = acc2[i][j];
                r[j] = __uint_as_float((unsigned)(u & 0xffffffffu)) +
                       __uint_as_float((unsigned)(u >> 32));
            }
            float* op = out + (size_t)row * DIM + colBase;
            #pragma unroll
            for (int j2 = 0; j2 < TN / 2; j2++) {
                float2 v;
                v.x = r[2 * j2 + 0] + bias[colBase + 2 * j2 + 0];
                v.y = r[2 * j2 + 1] + bias[colBase + 2 * j2 + 1];
                if (ACCUM) {
                    float2 prev = *(float2*)(op + 2 * j2);
                    v.x += prev.x;
                    v.y += prev.y;
                }
                *(float2*)(op + 2 * j2) = v;
            }
        }
    }
}

// ---------------------------------------------------------------------------
extern "C" void kernel_launch(void* const* d_in, const int* in_sizes, int n_in,
                              void* d_out, int out_size) {
    const float* x        = (const float*)d_in[0];
    const int*   ei       = (const int*)d_in[1];
    const float* W_self   = (const float*)d_in[2];
    const float* b_self   = (const float*)d_in[3];
    const float* W_neigh  = (const float*)d_in[4];
    const float* b_neigh  = (const float*)d_in[5];
    float*       out      = (float*)d_out;

    static cudaStream_t s2 = nullptr;
    static cudaEvent_t evFork = nullptr, evJoin = nullptr;
    static void* cnt_ptr = nullptr;
    static float* agg_f = nullptr;
    if (!s2) {
        cudaStreamCreateWithFlags(&s2, cudaStreamNonBlocking);
        cudaEventCreateWithFlags(&evFork, cudaEventDisableTiming);
        cudaEventCreateWithFlags(&evJoin, cudaEventDisableTiming);
        cudaGetSymbolAddress(&cnt_ptr, g_cnt);
        void* p; cudaGetSymbolAddress(&p, g_agg);
        agg_f = (float*)p;
    }

    // Fork: self-GEMM (independent of aggregation) on s2.
    cudaEventRecord(evFork, 0);
    cudaStreamWaitEvent(s2, evFork, 0);
    gemm_half<false><<<GEMM_BLOCKS, GT, 0, s2>>>(x, W_self, b_self, out);

    // Main stream: CSR build + gather.
    cudaMemsetAsync(cnt_ptr, 0, (size_t)N_NODES * sizeof(int));
    hist_kernel<<<(N_EDGES + 255) / 256, 256>>>(ei);
    scanA_kernel<<<SCAN_B, SCAN_T>>>();
    scanB_kernel<<<1, 128>>>();
    scanC_kernel<<<(N_NODES + 255) / 256, 256>>>();
    fill_kernel<<<(N_EDGES + 255) / 256, 256>>>(ei);
    gather_kernel<<<(N_NODES + 1) / 2, 192>>>(x);

    // Join: neigh-GEMM needs gather (stream order) + self-GEMM (event).
    cudaEventRecord(evJoin, s2);
    cudaStreamWaitEvent(0, evJoin, 0);
    gemm_half<true><<<GEMM_BLOCKS, GT>>>(agg_f, W_neigh, b_neigh, out);
}